// round 11
// baseline (speedup 1.0000x reference)
#include <cuda_runtime.h>
#include <cstdint>

// Problem constants (fixed for rotary_13872744366393):
//   x: (4, 8192, 1024) f32, matrix: (64,64), thetas: (32), tscale: (1),
//   invf: (32), pairs: (32,2) int32. out: (4, 8192, 1024) f32.
#define HEADS 16
#define D     64
#define ROTN  32
#define SEQ   8192

// B = M in tf32 hi/lo split, padded row stride 68 floats (272 B) for
// conflict-free fragment LDS. g_B*(k, n) at [k * 68 + n].
#define B_STRIDE 68
__device__ float g_Bhi[64 * B_STRIDE];
__device__ float g_Blo[64 * B_STRIDE];

// tf32 round (rna)
__device__ __forceinline__ uint32_t f2tf32(float x) {
    uint32_t r;
    asm("cvt.rna.tf32.f32 %0, %1;" : "=r"(r) : "f"(x));
    return r;
}

// m16n8k8 tf32 MMA, D = A@B + D (fp32 accum)
#define MMA_TF32(d, a, b)                                                     \
    asm volatile("mma.sync.aligned.m16n8k8.row.col.f32.tf32.tf32.f32 "        \
                 "{%0,%1,%2,%3}, {%4,%5,%6,%7}, {%8,%9}, {%0,%1,%2,%3};"      \
                 : "+f"((d)[0]), "+f"((d)[1]), "+f"((d)[2]), "+f"((d)[3])     \
                 : "r"((a)[0]), "r"((a)[1]), "r"((a)[2]), "r"((a)[3]),        \
                   "r"((b)[0]), "r"((b)[1]))

// ---------------------------------------------------------------------------
// Kernel 1: build M = G_comb @ matrix; emit tf32 hi/lo split of M.
// G_comb = I @ G_0 @ ... @ G_31 ; right-multiplying by G_q updates COLUMNS:
//   col_i' = col_i*c + col_j*s ;  col_j' = -col_i*s + col_j*c
// Degenerate i==j (JAX .at sequence leaves G[i,i] = sin): col_i' = col_i*s
// ---------------------------------------------------------------------------
__global__ void build_M_kernel(const float* __restrict__ matrix,
                               const float* __restrict__ thetas,
                               const float* __restrict__ tscale,
                               const int*   __restrict__ pairs) {
    __shared__ float Gs[64][65];
    __shared__ float Mat[64][64];
    __shared__ float Msh[64][64];
    __shared__ float ssin[ROTN], scos[ROTN];
    __shared__ int   sij[ROTN][2];
    const int tid = threadIdx.x;   // 256 threads

    for (int i = tid; i < 64 * 64; i += 256)
        Mat[i >> 6][i & 63] = matrix[i];

    if (tid < ROTN) {                      // sincos once, not per-row
        const float th = thetas[tid] * tscale[0];
        float s, c;
        sincosf(th, &s, &c);
        ssin[tid] = s;
        scos[tid] = c;
        sij[tid][0] = pairs[2 * tid];
        sij[tid][1] = pairs[2 * tid + 1];
    }
    if (tid < 64) {
        #pragma unroll
        for (int k = 0; k < 64; k++) Gs[tid][k] = (tid == k) ? 1.0f : 0.0f;
    }
    __syncthreads();

    if (tid < 64) {
        for (int q = 0; q < ROTN; q++) {
            const int   i = sij[q][0];
            const int   j = sij[q][1];
            const float s = ssin[q];
            const float c = scos[q];
            const float ai = Gs[tid][i];
            const float aj = Gs[tid][j];
            if (i != j) {
                Gs[tid][i] = ai * c + aj * s;
                Gs[tid][j] = -ai * s + aj * c;
            } else {
                Gs[tid][i] = ai * s;
            }
        }
    }
    __syncthreads();

    {
        const int r  = tid >> 2;
        const int qq = tid & 3;
        float gr[64];
        #pragma unroll
        for (int k = 0; k < 64; k++) gr[k] = Gs[r][k];
        #pragma unroll
        for (int n0 = 0; n0 < 16; n0++) {
            const int n = qq * 16 + n0;
            float acc = 0.0f;
            #pragma unroll
            for (int k = 0; k < 64; k++) acc = fmaf(gr[k], Mat[k][n], acc);
            Msh[r][n] = acc;
        }
    }
    __syncthreads();

    // tf32 hi/lo split, padded stride
    for (int idx = tid; idx < 64 * 64; idx += 256) {
        const int k = idx >> 6, n = idx & 63;
        const float m  = Msh[k][n];
        const float hi = __uint_as_float(f2tf32(m));
        const float lo = __uint_as_float(f2tf32(m - hi));
        g_Bhi[k * B_STRIDE + n] = hi;
        g_Blo[k * B_STRIDE + n] = lo;
    }
}

// ---------------------------------------------------------------------------
// Kernel 2: tf32 mma.sync GEMM (3-term compensated) + fused RoPE epilogue.
// CTA = 128 threads (4 warps), tile = 128 rows x 64 cols, K = 64.
// Warp w: rows [w*32, w*32+32) = two m16 tiles. 8 n8-tiles cover 64 cols.
// K loop: 8 steps of k8. Per (k-step, n-tile): 2 m-tiles x 3 terms = 6 MMAs.
// A staged fp32 in smem (row stride 68 floats, conflict-free frag loads),
// split to tf32 hi/lo in registers. B hi/lo pre-split by build kernel.
// Epilogue: c0/c1 of each acc frag = (y[2m], y[2m+1]) for m = 4j+tig ->
// one RoPE pair per thread per tile; *sqrt(1024)=32.
// ---------------------------------------------------------------------------
#define A_STRIDE 68                                // floats
#define SM_A     0                                 // 128*68*4 = 34816
#define SM_BH    (128 * A_STRIDE * 4)              // 34816
#define SM_BL    (SM_BH + 64 * B_STRIDE * 4)       // 34816 + 17408 = 52224
#define SM_SC    (SM_BL + 64 * B_STRIDE * 4)       // 69632
#define SMEM_DYN (SM_SC + 8 * 32 * 8)              // + 2048 = 71680

__global__ __launch_bounds__(128, 3)
void rotary_mma(const float* __restrict__ x,
                const float* __restrict__ invf,
                float* __restrict__ out) {
    extern __shared__ __align__(16) char dsm[];
    float* Asm  = (float*)(dsm + SM_A);
    float* Bhs  = (float*)(dsm + SM_BH);
    float* Bls  = (float*)(dsm + SM_BL);
    float2* sc  = (float2*)(dsm + SM_SC);

    const int tid  = threadIdx.x;
    const int w    = tid >> 5;
    const int lane = tid & 31;
    const int g    = lane >> 2;     // groupID 0..7
    const int tig  = lane & 3;      // threadID_in_group 0..3

    // ---- stage A: 128 rows x 256B, LDG.128 -> STS.128, row-major pad 68 ----
    {
        const uint4* xg = (const uint4*)(x + (size_t)blockIdx.x * 128 * 64);
        #pragma unroll
        for (int i = 0; i < 16; i++) {
            const int idx = i * 128 + tid;        // 16B chunk id, 2048 total
            const int row = idx >> 4;
            const int kq  = idx & 15;
            *(uint4*)(Asm + row * A_STRIDE + kq * 4) = xg[idx];
        }
    }

    // ---- stage B hi/lo (64*68 floats each = 1088 uint4 each) ----
    {
        const uint4* bh = (const uint4*)g_Bhi;
        const uint4* bl = (const uint4*)g_Blo;
        uint4* dh = (uint4*)Bhs;
        uint4* dl = (uint4*)Bls;
        #pragma unroll
        for (int i = 0; i < 9; i++) {
            const int idx = tid + 128 * i;
            if (idx < 64 * B_STRIDE / 4) {
                dh[idx] = bh[idx];
                dl[idx] = bl[idx];
            }
        }
    }

    // ---- sincos table: 8 tokens x 32 freqs ----
    {
        #pragma unroll
        for (int e = 0; e < 2; e++) {
            const int idx = tid * 2 + e;          // 256 entries
            const int t = idx >> 5, m = idx & 31;
            const int pos = (blockIdx.x * 8 + t) & (SEQ - 1);
            float sn, cs;
            sincosf((float)pos * invf[m], &sn, &cs);
            sc[idx] = make_float2(sn, cs);
        }
    }
    __syncthreads();

    // ---- mainloop ----
    float acc[2][8][4];
    #pragma unroll
    for (int mt = 0; mt < 2; mt++)
        #pragma unroll
        for (int j = 0; j < 8; j++)
            #pragma unroll
            for (int q = 0; q < 4; q++) acc[mt][j][q] = 0.0f;

    // thread-invariant bases
    const float* Abase = Asm + (w * 32 + g) * A_STRIDE + tig;    // a0 of mt=0
    const float* Bbase = Bhs + tig * B_STRIDE + g;               // b0 hi
    const float* Blbase = Bls + tig * B_STRIDE + g;              // b0 lo

    #pragma unroll
    for (int kt = 0; kt < 8; kt++) {
        // A fragments for both m-tiles, split hi/lo in regs
        uint32_t ah[2][4], al[2][4];
        #pragma unroll
        for (int mt = 0; mt < 2; mt++) {
            const float* ap = Abase + mt * 16 * A_STRIDE + kt * 8;
            const float f0 = ap[0];                      // row g,    k0+tig
            const float f1 = ap[8 * A_STRIDE];           // row g+8,  k0+tig
            const float f2 = ap[4];                      // row g,    k0+tig+4
            const float f3 = ap[8 * A_STRIDE + 4];       // row g+8,  k0+tig+4
            ah[mt][0] = f2tf32(f0);
            ah[mt][1] = f2tf32(f1);
            ah[mt][2] = f2tf32(f2);
            ah[mt][3] = f2tf32(f3);
            al[mt][0] = f2tf32(f0 - __uint_as_float(ah[mt][0]));
            al[mt][1] = f2tf32(f1 - __uint_as_float(ah[mt][1]));
            al[mt][2] = f2tf32(f2 - __uint_as_float(ah[mt][2]));
            al[mt][3] = f2tf32(f3 - __uint_as_float(ah[mt][3]));
        }
        #pragma unroll
        for (int j = 0; j < 8; j++) {
            uint32_t bh[2], bl[2];
            const float* bp  = Bbase  + kt * 8 * B_STRIDE + j * 8;
            const float* blp = Blbase + kt * 8 * B_STRIDE + j * 8;
            bh[0] = __float_as_uint(bp[0]);              // k0+tig,   n=8j+g
            bh[1] = __float_as_uint(bp[4 * B_STRIDE]);   // k0+tig+4, n=8j+g
            bl[0] = __float_as_uint(blp[0]);
            bl[1] = __float_as_uint(blp[4 * B_STRIDE]);
            #pragma unroll
            for (int mt = 0; mt < 2; mt++) {
                MMA_TF32(acc[mt][j], ah[mt], bh);        // xh @ Mh
                MMA_TF32(acc[mt][j], al[mt], bh);        // xl @ Mh
                MMA_TF32(acc[mt][j], ah[mt], bl);        // xh @ Ml
            }
        }
    }

    // ---- epilogue: RoPE + *32, scattered STG.32 ----
    // acc[mt][j]: rows (w*32+mt*16+g, +8), cols (8j+2tig, 8j+2tig+1)
    //   = y-pair (y[2m], y[2m+1]) with m = 4j+tig; token = 2w+mt.
    #pragma unroll
    for (int mt = 0; mt < 2; mt++) {
        const int tok = 2 * w + mt;
        const size_t row0 = (size_t)blockIdx.x * 128 + w * 32 + mt * 16 + g;
        float* o0 = out + row0 * 64;
        float* o1 = out + (row0 + 8) * 64;
        #pragma unroll
        for (int j = 0; j < 8; j++) {
            const int m = 4 * j + tig;
            const float2 scm = sc[tok * 32 + m];         // (sin, cos)
            const float* a = acc[mt][j];
            o0[m]      = (a[0] * scm.y - a[1] * scm.x) * 32.0f;
            o0[m + 32] = (a[0] * scm.x + a[1] * scm.y) * 32.0f;
            o1[m]      = (a[2] * scm.y - a[3] * scm.x) * 32.0f;
            o1[m + 32] = (a[2] * scm.x + a[3] * scm.y) * 32.0f;
        }
    }
}

// ---------------------------------------------------------------------------
extern "C" void kernel_launch(void* const* d_in, const int* in_sizes, int n_in,
                              void* d_out, int out_size) {
    const float* x      = (const float*)d_in[0];
    const float* matrix = (const float*)d_in[1];
    const float* thetas = (const float*)d_in[2];
    const float* tscale = (const float*)d_in[3];
    const float* invf   = (const float*)d_in[4];
    const int*   pairs  = (const int*)d_in[5];
    float* out = (float*)d_out;

    static bool attr_set = false;
    if (!attr_set) {
        cudaFuncSetAttribute(rotary_mma,
                             cudaFuncAttributeMaxDynamicSharedMemorySize,
                             SMEM_DYN);
        attr_set = true;
    }

    const int nrows  = in_sizes[0] / D;      // 524288
    const int blocks = nrows / 128;          // 4096

    build_M_kernel<<<1, 256>>>(matrix, thetas, tscale, pairs);
    rotary_mma<<<blocks, 128, SMEM_DYN>>>(x, invf, out);
}

// round 12
// speedup vs baseline: 1.0907x; 1.0907x over previous
#include <cuda_runtime.h>
#include <cstdint>

// Problem constants (fixed for rotary_13872744366393):
//   x: (4, 8192, 1024) f32, matrix: (64,64), thetas: (32), tscale: (1),
//   invf: (32), pairs: (32,2) int32. out: (4, 8192, 1024) f32.
#define HEADS 16
#define D     64
#define ROTN  32
#define SEQ   8192

// Pre-built tf32 B fragments for mma.m16n8k8:
//   g_Bfrag[(kt*8 + j)*32 + lane] = {Bhi(k,n), Bhi(k+4,n), Blo(k,n), Blo(k+4,n)}
// with k = 8*kt + tig, n = 8*j + g, lane = 4*g' ... (g = lane>>2, tig = lane&3).
__device__ float4 g_Bfrag[8 * 8 * 32];     // 32 KB

// tf32 round (rna)
__device__ __forceinline__ uint32_t f2tf32(float x) {
    uint32_t r;
    asm("cvt.rna.tf32.f32 %0, %1;" : "=r"(r) : "f"(x));
    return r;
}

// m16n8k8 tf32 MMA, D = A@B + D (fp32 accum)
#define MMA_TF32(d, a, b)                                                     \
    asm volatile("mma.sync.aligned.m16n8k8.row.col.f32.tf32.tf32.f32 "        \
                 "{%0,%1,%2,%3}, {%4,%5,%6,%7}, {%8,%9}, {%0,%1,%2,%3};"      \
                 : "+f"((d)[0]), "+f"((d)[1]), "+f"((d)[2]), "+f"((d)[3])     \
                 : "r"((a)[0]), "r"((a)[1]), "r"((a)[2]), "r"((a)[3]),        \
                   "r"((b)[0]), "r"((b)[1]))

// ---------------------------------------------------------------------------
// Kernel 1: build M = G_comb @ matrix; emit tf32 hi/lo B FRAGMENTS.
// G_comb = I @ G_0 @ ... @ G_31 ; right-multiplying by G_q updates COLUMNS:
//   col_i' = col_i*c + col_j*s ;  col_j' = -col_i*s + col_j*c
// Degenerate i==j (JAX .at sequence leaves G[i,i] = sin): col_i' = col_i*s
// ---------------------------------------------------------------------------
__global__ void build_M_kernel(const float* __restrict__ matrix,
                               const float* __restrict__ thetas,
                               const float* __restrict__ tscale,
                               const int*   __restrict__ pairs) {
    __shared__ float Gs[64][65];
    __shared__ float Mat[64][64];
    __shared__ float Msh[64][64];
    __shared__ float ssin[ROTN], scos[ROTN];
    __shared__ int   sij[ROTN][2];
    const int tid = threadIdx.x;   // 256 threads

    for (int i = tid; i < 64 * 64; i += 256)
        Mat[i >> 6][i & 63] = matrix[i];

    if (tid < ROTN) {                      // sincos once, not per-row
        const float th = thetas[tid] * tscale[0];
        float s, c;
        sincosf(th, &s, &c);
        ssin[tid] = s;
        scos[tid] = c;
        sij[tid][0] = pairs[2 * tid];
        sij[tid][1] = pairs[2 * tid + 1];
    }
    if (tid < 64) {
        #pragma unroll
        for (int k = 0; k < 64; k++) Gs[tid][k] = (tid == k) ? 1.0f : 0.0f;
    }
    __syncthreads();

    if (tid < 64) {
        for (int q = 0; q < ROTN; q++) {
            const int   i = sij[q][0];
            const int   j = sij[q][1];
            const float s = ssin[q];
            const float c = scos[q];
            const float ai = Gs[tid][i];
            const float aj = Gs[tid][j];
            if (i != j) {
                Gs[tid][i] = ai * c + aj * s;
                Gs[tid][j] = -ai * s + aj * c;
            } else {
                Gs[tid][i] = ai * s;
            }
        }
    }
    __syncthreads();

    {
        const int r  = tid >> 2;
        const int qq = tid & 3;
        float gr[64];
        #pragma unroll
        for (int k = 0; k < 64; k++) gr[k] = Gs[r][k];
        #pragma unroll
        for (int n0 = 0; n0 < 16; n0++) {
            const int n = qq * 16 + n0;
            float acc = 0.0f;
            #pragma unroll
            for (int k = 0; k < 64; k++) acc = fmaf(gr[k], Mat[k][n], acc);
            Msh[r][n] = acc;
        }
    }
    __syncthreads();

    // emit fragment-ordered B (hi/lo tf32)
    for (int idx = tid; idx < 8 * 8 * 32; idx += 256) {
        const int frag = idx >> 5;           // kt*8 + j
        const int lane = idx & 31;
        const int kt = frag >> 3, j = frag & 7;
        const int g = lane >> 2, tg = lane & 3;
        const int k = kt * 8 + tg;
        const int n = 8 * j + g;
        const float m0 = Msh[k][n];
        const float m1 = Msh[k + 4][n];
        const float h0 = __uint_as_float(f2tf32(m0));
        const float h1 = __uint_as_float(f2tf32(m1));
        const float l0 = __uint_as_float(f2tf32(m0 - h0));
        const float l1 = __uint_as_float(f2tf32(m1 - h1));
        g_Bfrag[idx] = make_float4(h0, h1, l0, l1);
    }
}

// ---------------------------------------------------------------------------
// Kernel 2: tf32 mma.sync GEMM (3-term compensated) + fused RoPE epilogue.
// CTA = 128 threads (4 warps), tile = 128 rows x 64 cols, K = 64.
// Warp w: rows [w*32, w*32+32) = two m16 tiles; 8 n8-tiles cover 64 cols.
// A staged in smem with PAIR-PERMUTED columns (per 8-col group order
// 0,4,1,5,2,6,3,7) so an A fragment's (k, k+4) pair is one LDS.64.
// B fragments pre-built (one LDS.128 per (kt,j) loads hi+lo for both k's).
// Epilogue: RoPE in regs -> conflict-free STS.32 scatter into the A buffer
// -> coalesced LDS.128 + STG.128 (R11's scattered STG.32 was the regression).
// ---------------------------------------------------------------------------
#define A_STRIDE 68                                // floats, padded
#define SM_A     0                                 // 128*68*4 = 34816 B
#define SM_BF    (128 * A_STRIDE * 4)              // 34816
#define SM_SC    (SM_BF + 8 * 8 * 32 * 16)         // 34816 + 32768 = 67584
#define SMEM_DYN (SM_SC + 8 * 32 * 8)              // + 2048 = 69632

__global__ __launch_bounds__(128, 3)
void rotary_mma(const float* __restrict__ x,
                const float* __restrict__ invf,
                float* __restrict__ out) {
    extern __shared__ __align__(16) char dsm[];
    float*  Asm = (float*)(dsm + SM_A);
    float4* Bfs = (float4*)(dsm + SM_BF);
    float2* sc  = (float2*)(dsm + SM_SC);

    const int tid  = threadIdx.x;
    const int w    = tid >> 5;
    const int lane = tid & 31;
    const int g    = lane >> 2;     // groupID 0..7
    const int tig  = lane & 3;      // threadID_in_group 0..3

    // ---- stage A: pair-permute columns per 8-group: (c0,c4,c1,c5),(c2,c6,c3,c7)
    {
        const float4* xg = (const float4*)(x + (size_t)blockIdx.x * 128 * 64);
        #pragma unroll
        for (int i = 0; i < 8; i++) {
            const int idx = i * 128 + tid;        // 32B group id, 1024 total
            const int row = idx >> 3;
            const int q   = idx & 7;              // 8-col group within row
            const float4 v0 = xg[2 * idx];        // cols 8q+0..3
            const float4 v1 = xg[2 * idx + 1];    // cols 8q+4..7
            float* dst = Asm + row * A_STRIDE + q * 8;
            *(float4*)dst       = make_float4(v0.x, v1.x, v0.y, v1.y);
            *(float4*)(dst + 4) = make_float4(v0.z, v1.z, v0.w, v1.w);
        }
    }

    // ---- stage B fragments: 2048 float4, 16 per thread ----
    {
        #pragma unroll
        for (int i = 0; i < 16; i++) {
            const int idx = tid + 128 * i;
            Bfs[idx] = g_Bfrag[idx];
        }
    }

    // ---- sincos table: 8 tokens x 32 freqs ----
    {
        #pragma unroll
        for (int e = 0; e < 2; e++) {
            const int idx = tid * 2 + e;          // 256 entries
            const int t = idx >> 5, m = idx & 31;
            const int pos = (blockIdx.x * 8 + t) & (SEQ - 1);
            float sn, cs;
            sincosf((float)pos * invf[m], &sn, &cs);
            sc[idx] = make_float2(sn, cs);
        }
    }
    __syncthreads();

    // ---- mainloop ----
    float acc[2][8][4];
    #pragma unroll
    for (int mt = 0; mt < 2; mt++)
        #pragma unroll
        for (int j = 0; j < 8; j++)
            #pragma unroll
            for (int q = 0; q < 4; q++) acc[mt][j][q] = 0.0f;

    const float* Abase = Asm + (w * 32 + g) * A_STRIDE + 2 * tig;
    const float4* Bbase = Bfs + lane;

    #pragma unroll
    for (int kt = 0; kt < 8; kt++) {
        // A fragments, hi/lo split in regs. LDS.64 gives the (k, k+4) pair.
        uint32_t ah[2][4], al[2][4];
        #pragma unroll
        for (int mt = 0; mt < 2; mt++) {
            const float* ap = Abase + mt * 16 * A_STRIDE + kt * 8;
            const float2 p0 = *(const float2*)ap;                    // row g
            const float2 p1 = *(const float2*)(ap + 8 * A_STRIDE);   // row g+8
            ah[mt][0] = f2tf32(p0.x);
            ah[mt][1] = f2tf32(p1.x);
            ah[mt][2] = f2tf32(p0.y);
            ah[mt][3] = f2tf32(p1.y);
            al[mt][0] = f2tf32(p0.x - __uint_as_float(ah[mt][0]));
            al[mt][1] = f2tf32(p1.x - __uint_as_float(ah[mt][1]));
            al[mt][2] = f2tf32(p0.y - __uint_as_float(ah[mt][2]));
            al[mt][3] = f2tf32(p1.y - __uint_as_float(ah[mt][3]));
        }
        #pragma unroll
        for (int j = 0; j < 8; j++) {
            const float4 bf = Bbase[(kt * 8 + j) * 32];  // LDS.128
            uint32_t bh[2], bl[2];
            bh[0] = __float_as_uint(bf.x);
            bh[1] = __float_as_uint(bf.y);
            bl[0] = __float_as_uint(bf.z);
            bl[1] = __float_as_uint(bf.w);
            #pragma unroll
            for (int mt = 0; mt < 2; mt++) {
                MMA_TF32(acc[mt][j], ah[mt], bh);        // xh @ Mh
                MMA_TF32(acc[mt][j], al[mt], bh);        // xl @ Mh
                MMA_TF32(acc[mt][j], ah[mt], bl);        // xh @ Ml
            }
        }
    }

    // ---- epilogue: RoPE + *32 in regs, STS.32 scatter (conflict-free),
    //      then coalesced LDS.128 -> STG.128 via the A buffer ----
    __syncthreads();                                     // A reads done
    #pragma unroll
    for (int mt = 0; mt < 2; mt++) {
        const int tok = 2 * w + mt;
        const int r0 = w * 32 + mt * 16 + g;
        #pragma unroll
        for (int j = 0; j < 8; j++) {
            const int m = 4 * j + tig;
            const float2 scm = sc[tok * 32 + m];         // (sin, cos)
            const float* a = acc[mt][j];
            Asm[r0 * A_STRIDE + m]            = (a[0] * scm.y - a[1] * scm.x) * 32.0f;
            Asm[r0 * A_STRIDE + m + 32]       = (a[0] * scm.x + a[1] * scm.y) * 32.0f;
            Asm[(r0 + 8) * A_STRIDE + m]      = (a[2] * scm.y - a[3] * scm.x) * 32.0f;
            Asm[(r0 + 8) * A_STRIDE + m + 32] = (a[2] * scm.x + a[3] * scm.y) * 32.0f;
        }
    }
    __syncthreads();

    {
        float4* og = (float4*)(out + (size_t)blockIdx.x * 128 * 64);
        #pragma unroll
        for (int i = 0; i < 16; i++) {
            const int idx = i * 128 + tid;        // 16B chunk id, 2048 total
            const int row = idx >> 4;
            const int kq  = idx & 15;
            og[idx] = *(const float4*)(Asm + row * A_STRIDE + kq * 4);
        }
    }
}

// ---------------------------------------------------------------------------
extern "C" void kernel_launch(void* const* d_in, const int* in_sizes, int n_in,
                              void* d_out, int out_size) {
    const float* x      = (const float*)d_in[0];
    const float* matrix = (const float*)d_in[1];
    const float* thetas = (const float*)d_in[2];
    const float* tscale = (const float*)d_in[3];
    const float* invf   = (const float*)d_in[4];
    const int*   pairs  = (const int*)d_in[5];
    float* out = (float*)d_out;

    static bool attr_set = false;
    if (!attr_set) {
        cudaFuncSetAttribute(rotary_mma,
                             cudaFuncAttributeMaxDynamicSharedMemorySize,
                             SMEM_DYN);
        attr_set = true;
    }

    const int nrows  = in_sizes[0] / D;      // 524288
    const int blocks = nrows / 128;          // 4096

    build_M_kernel<<<1, 256>>>(matrix, thetas, tscale, pairs);
    rotary_mma<<<blocks, 128, SMEM_DYN>>>(x, invf, out);
}

// round 13
// speedup vs baseline: 1.2135x; 1.1126x over previous
#include <cuda_runtime.h>
#include <cstdint>

// Problem constants (fixed for rotary_13872744366393):
//   x: (4, 8192, 1024) f32, matrix: (64,64), thetas: (32), tscale: (1),
//   invf: (32), pairs: (32,2) int32. out: (4, 8192, 1024) f32.
#define HEADS 16
#define D     64
#define ROTN  32
#define SEQ   8192

// Pre-built tf32 B fragments for mma.m16n8k8:
//   g_Bfrag[(kt*8 + j)*32 + lane] = {Bhi(k,n), Bhi(k+4,n), Blo(k,n), Blo(k+4,n)}
// with k = 8*kt + tig, n = 8*j + g  (g = lane>>2, tig = lane&3).
__device__ float4 g_Bfrag[8 * 8 * 32];     // 32 KB

// tf32 round (rna)
__device__ __forceinline__ uint32_t f2tf32(float x) {
    uint32_t r;
    asm("cvt.rna.tf32.f32 %0, %1;" : "=r"(r) : "f"(x));
    return r;
}

// m16n8k8 tf32 MMA, D = A@B + D (fp32 accum)
#define MMA_TF32(d, a, b)                                                     \
    asm volatile("mma.sync.aligned.m16n8k8.row.col.f32.tf32.tf32.f32 "        \
                 "{%0,%1,%2,%3}, {%4,%5,%6,%7}, {%8,%9}, {%0,%1,%2,%3};"      \
                 : "+f"((d)[0]), "+f"((d)[1]), "+f"((d)[2]), "+f"((d)[3])     \
                 : "r"((a)[0]), "r"((a)[1]), "r"((a)[2]), "r"((a)[3]),        \
                   "r"((b)[0]), "r"((b)[1]))

// ---------------------------------------------------------------------------
// Kernel 1: build M = G_comb @ matrix; emit tf32 hi/lo B FRAGMENTS.
// G_comb = I @ G_0 @ ... @ G_31 ; right-multiplying by G_q updates COLUMNS:
//   col_i' = col_i*c + col_j*s ;  col_j' = -col_i*s + col_j*c
// Degenerate i==j (JAX .at sequence leaves G[i,i] = sin): col_i' = col_i*s
// ---------------------------------------------------------------------------
__global__ void build_M_kernel(const float* __restrict__ matrix,
                               const float* __restrict__ thetas,
                               const float* __restrict__ tscale,
                               const int*   __restrict__ pairs) {
    __shared__ float Gs[64][65];
    __shared__ float Mat[64][64];
    __shared__ float Msh[64][64];
    __shared__ float ssin[ROTN], scos[ROTN];
    __shared__ int   sij[ROTN][2];
    const int tid = threadIdx.x;   // 256 threads

    for (int i = tid; i < 64 * 64; i += 256)
        Mat[i >> 6][i & 63] = matrix[i];

    if (tid < ROTN) {                      // sincos once, not per-row
        const float th = thetas[tid] * tscale[0];
        float s, c;
        sincosf(th, &s, &c);
        ssin[tid] = s;
        scos[tid] = c;
        sij[tid][0] = pairs[2 * tid];
        sij[tid][1] = pairs[2 * tid + 1];
    }
    if (tid < 64) {
        #pragma unroll
        for (int k = 0; k < 64; k++) Gs[tid][k] = (tid == k) ? 1.0f : 0.0f;
    }
    __syncthreads();

    if (tid < 64) {
        for (int q = 0; q < ROTN; q++) {
            const int   i = sij[q][0];
            const int   j = sij[q][1];
            const float s = ssin[q];
            const float c = scos[q];
            const float ai = Gs[tid][i];
            const float aj = Gs[tid][j];
            if (i != j) {
                Gs[tid][i] = ai * c + aj * s;
                Gs[tid][j] = -ai * s + aj * c;
            } else {
                Gs[tid][i] = ai * s;
            }
        }
    }
    __syncthreads();

    {
        const int r  = tid >> 2;
        const int qq = tid & 3;
        float gr[64];
        #pragma unroll
        for (int k = 0; k < 64; k++) gr[k] = Gs[r][k];
        #pragma unroll
        for (int n0 = 0; n0 < 16; n0++) {
            const int n = qq * 16 + n0;
            float acc = 0.0f;
            #pragma unroll
            for (int k = 0; k < 64; k++) acc = fmaf(gr[k], Mat[k][n], acc);
            Msh[r][n] = acc;
        }
    }
    __syncthreads();

    // emit fragment-ordered B (hi/lo tf32)
    for (int idx = tid; idx < 8 * 8 * 32; idx += 256) {
        const int frag = idx >> 5;           // kt*8 + j
        const int lane = idx & 31;
        const int kt = frag >> 3, j = frag & 7;
        const int g = lane >> 2, tg = lane & 3;
        const int k = kt * 8 + tg;
        const int n = 8 * j + g;
        const float m0 = Msh[k][n];
        const float m1 = Msh[k + 4][n];
        const float h0 = __uint_as_float(f2tf32(m0));
        const float h1 = __uint_as_float(f2tf32(m1));
        const float l0 = __uint_as_float(f2tf32(m0 - h0));
        const float l1 = __uint_as_float(f2tf32(m1 - h1));
        g_Bfrag[idx] = make_float4(h0, h1, l0, l1);
    }
}

// ---------------------------------------------------------------------------
// Kernel 2: tf32 mma.sync GEMM (3-term compensated) + fused RoPE epilogue.
// CTA = 128 threads (4 warps), tile = 128 rows x 64 cols, K = 64.
// Warp w: rows [w*32, w*32+32) = two m16 tiles; 8 n8-tiles cover 64 cols.
// A staged in smem with PAIR-PERMUTED columns (per 8-col group order
// 0,4,1,5,2,6,3,7) so an A fragment's (k, k+4) pair is one LDS.64.
// B fragments pre-built (one LDS.128 per (kt,j) loads hi+lo for both k's).
// __launch_bounds__(128, 2): 256-reg budget; A raw operands and B fragments
// are EXPLICITLY double-buffered across kt (R12 sat at the 3-CTA 168-reg
// ceiling -> no pipelining -> issue 22.8%). Epilogue: RoPE in regs ->
// conflict-free STS.32 scatter into the A buffer -> LDS.128 + STG.128.
// ---------------------------------------------------------------------------
#define A_STRIDE 68                                // floats, padded
#define SM_A     0                                 // 128*68*4 = 34816 B
#define SM_BF    (128 * A_STRIDE * 4)              // 34816
#define SM_SC    (SM_BF + 8 * 8 * 32 * 16)         // 34816 + 32768 = 67584
#define SMEM_DYN (SM_SC + 8 * 32 * 8)              // + 2048 = 69632

__global__ __launch_bounds__(128, 2)
void rotary_mma(const float* __restrict__ x,
                const float* __restrict__ invf,
                float* __restrict__ out) {
    extern __shared__ __align__(16) char dsm[];
    float*  Asm = (float*)(dsm + SM_A);
    float4* Bfs = (float4*)(dsm + SM_BF);
    float2* sc  = (float2*)(dsm + SM_SC);

    const int tid  = threadIdx.x;
    const int w    = tid >> 5;
    const int lane = tid & 31;
    const int g    = lane >> 2;     // groupID 0..7
    const int tig  = lane & 3;      // threadID_in_group 0..3

    // ---- stage A: pair-permute columns per 8-group: (c0,c4,c1,c5),(c2,c6,c3,c7)
    {
        const float4* xg = (const float4*)(x + (size_t)blockIdx.x * 128 * 64);
        #pragma unroll
        for (int i = 0; i < 8; i++) {
            const int idx = i * 128 + tid;        // 32B group id, 1024 total
            const int row = idx >> 3;
            const int q   = idx & 7;              // 8-col group within row
            const float4 v0 = xg[2 * idx];        // cols 8q+0..3
            const float4 v1 = xg[2 * idx + 1];    // cols 8q+4..7
            float* dst = Asm + row * A_STRIDE + q * 8;
            *(float4*)dst       = make_float4(v0.x, v1.x, v0.y, v1.y);
            *(float4*)(dst + 4) = make_float4(v0.z, v1.z, v0.w, v1.w);
        }
    }

    // ---- stage B fragments: 2048 float4, 16 per thread ----
    {
        #pragma unroll
        for (int i = 0; i < 16; i++) {
            const int idx = tid + 128 * i;
            Bfs[idx] = g_Bfrag[idx];
        }
    }

    // ---- sincos table: 8 tokens x 32 freqs ----
    {
        #pragma unroll
        for (int e = 0; e < 2; e++) {
            const int idx = tid * 2 + e;          // 256 entries
            const int t = idx >> 5, m = idx & 31;
            const int pos = (blockIdx.x * 8 + t) & (SEQ - 1);
            float sn, cs;
            sincosf((float)pos * invf[m], &sn, &cs);
            sc[idx] = make_float2(sn, cs);
        }
    }
    __syncthreads();

    // ---- mainloop: explicit double-buffered A raw + B fragments ----
    float acc[2][8][4];
    #pragma unroll
    for (int mt = 0; mt < 2; mt++)
        #pragma unroll
        for (int j = 0; j < 8; j++)
            #pragma unroll
            for (int q = 0; q < 4; q++) acc[mt][j][q] = 0.0f;

    const float* Abase = Asm + (w * 32 + g) * A_STRIDE + 2 * tig;
    const float4* Bbase = Bfs + lane;

    float2 pa0[2][2], pa1[2][2];   // [buf][mt]: rows g, g+8 raw (k,k+4) pairs
    float4 pb[2][8];               // [buf][j]: B fragments

    // prefetch kt = 0
    #pragma unroll
    for (int mt = 0; mt < 2; mt++) {
        const float* ap = Abase + mt * 16 * A_STRIDE;
        pa0[0][mt] = *(const float2*)ap;
        pa1[0][mt] = *(const float2*)(ap + 8 * A_STRIDE);
    }
    #pragma unroll
    for (int j = 0; j < 8; j++) pb[0][j] = Bbase[j * 32];

    #pragma unroll
    for (int kt = 0; kt < 8; kt++) {
        const int cur = kt & 1, nxt = cur ^ 1;
        if (kt < 7) {
            #pragma unroll
            for (int mt = 0; mt < 2; mt++) {
                const float* ap = Abase + mt * 16 * A_STRIDE + (kt + 1) * 8;
                pa0[nxt][mt] = *(const float2*)ap;
                pa1[nxt][mt] = *(const float2*)(ap + 8 * A_STRIDE);
            }
            #pragma unroll
            for (int j = 0; j < 8; j++)
                pb[nxt][j] = Bbase[((kt + 1) * 8 + j) * 32];
        }

        // convert current A to tf32 hi/lo fragments
        uint32_t ah[2][4], al[2][4];
        #pragma unroll
        for (int mt = 0; mt < 2; mt++) {
            const float2 p0 = pa0[cur][mt];
            const float2 p1 = pa1[cur][mt];
            ah[mt][0] = f2tf32(p0.x);
            ah[mt][1] = f2tf32(p1.x);
            ah[mt][2] = f2tf32(p0.y);
            ah[mt][3] = f2tf32(p1.y);
            al[mt][0] = f2tf32(p0.x - __uint_as_float(ah[mt][0]));
            al[mt][1] = f2tf32(p1.x - __uint_as_float(ah[mt][1]));
            al[mt][2] = f2tf32(p0.y - __uint_as_float(ah[mt][2]));
            al[mt][3] = f2tf32(p1.y - __uint_as_float(ah[mt][3]));
        }

        #pragma unroll
        for (int j = 0; j < 8; j++) {
            const float4 bf = pb[cur][j];
            uint32_t bh[2], bl[2];
            bh[0] = __float_as_uint(bf.x);
            bh[1] = __float_as_uint(bf.y);
            bl[0] = __float_as_uint(bf.z);
            bl[1] = __float_as_uint(bf.w);
            #pragma unroll
            for (int mt = 0; mt < 2; mt++) {
                MMA_TF32(acc[mt][j], ah[mt], bh);        // xh @ Mh
                MMA_TF32(acc[mt][j], al[mt], bh);        // xl @ Mh
                MMA_TF32(acc[mt][j], ah[mt], bl);        // xh @ Ml
            }
        }
    }

    // ---- epilogue: RoPE + *32 in regs, STS.32 scatter (conflict-free),
    //      then coalesced LDS.128 -> STG.128 via the A buffer ----
    __syncthreads();                                     // A reads done
    #pragma unroll
    for (int mt = 0; mt < 2; mt++) {
        const int tok = 2 * w + mt;
        const int r0 = w * 32 + mt * 16 + g;
        #pragma unroll
        for (int j = 0; j < 8; j++) {
            const int m = 4 * j + tig;
            const float2 scm = sc[tok * 32 + m];         // (sin, cos)
            const float* a = acc[mt][j];
            Asm[r0 * A_STRIDE + m]            = (a[0] * scm.y - a[1] * scm.x) * 32.0f;
            Asm[r0 * A_STRIDE + m + 32]       = (a[0] * scm.x + a[1] * scm.y) * 32.0f;
            Asm[(r0 + 8) * A_STRIDE + m]      = (a[2] * scm.y - a[3] * scm.x) * 32.0f;
            Asm[(r0 + 8) * A_STRIDE + m + 32] = (a[2] * scm.x + a[3] * scm.y) * 32.0f;
        }
    }
    __syncthreads();

    {
        float4* og = (float4*)(out + (size_t)blockIdx.x * 128 * 64);
        #pragma unroll
        for (int i = 0; i < 16; i++) {
            const int idx = i * 128 + tid;        // 16B chunk id, 2048 total
            const int row = idx >> 4;
            const int kq  = idx & 15;
            og[idx] = *(const float4*)(Asm + row * A_STRIDE + kq * 4);
        }
    }
}

// ---------------------------------------------------------------------------
extern "C" void kernel_launch(void* const* d_in, const int* in_sizes, int n_in,
                              void* d_out, int out_size) {
    const float* x      = (const float*)d_in[0];
    const float* matrix = (const float*)d_in[1];
    const float* thetas = (const float*)d_in[2];
    const float* tscale = (const float*)d_in[3];
    const float* invf   = (const float*)d_in[4];
    const int*   pairs  = (const int*)d_in[5];
    float* out = (float*)d_out;

    static bool attr_set = false;
    if (!attr_set) {
        cudaFuncSetAttribute(rotary_mma,
                             cudaFuncAttributeMaxDynamicSharedMemorySize,
                             SMEM_DYN);
        attr_set = true;
    }

    const int nrows  = in_sizes[0] / D;      // 524288
    const int blocks = nrows / 128;          // 4096

    build_M_kernel<<<1, 256>>>(matrix, thetas, tscale, pairs);
    rotary_mma<<<blocks, 128, SMEM_DYN>>>(x, invf, out);
}

// round 14
// speedup vs baseline: 1.4502x; 1.1950x over previous
#include <cuda_runtime.h>
#include <cstdint>

// Problem constants (fixed for rotary_13872744366393):
//   x: (4, 8192, 1024) f32, matrix: (64,64), thetas: (32), tscale: (1),
//   invf: (32), pairs: (32,2) int32. out: (4, 8192, 1024) f32.
#define HEADS 16
#define D     64
#define ROTN  32
#define SEQ   8192

// Pre-built bf16 B fragments for mma.m16n8k16:
//   g_Bfrag[(kt*8 + j)*32 + lane] = {bhi0, bhi1, blo0, blo1} (packed bf16x2)
//   bhi0 = (Mhi[k0][n], Mhi[k0+1][n]), bhi1 = (Mhi[k0+8][n], Mhi[k0+9][n])
// with k0 = kt*16 + 2*tig, n = 8*j + g  (g = lane>>2, tig = lane&3).
__device__ uint4 g_Bfrag[4 * 8 * 32];     // 16 KB

// pack two fp32 into bf16x2 (rn): low half = lo, high half = hi
__device__ __forceinline__ uint32_t pack_bf16x2(float lo, float hi) {
    uint32_t r;
    asm("cvt.rn.bf16x2.f32 %0, %1, %2;" : "=r"(r) : "f"(hi), "f"(lo));
    return r;
}
// bf16 (as the half of a packed u32) back to fp32 is just bit placement
__device__ __forceinline__ float bf_lo_f32(uint32_t p) {
    return __uint_as_float(p << 16);
}
__device__ __forceinline__ float bf_hi_f32(uint32_t p) {
    return __uint_as_float(p & 0xFFFF0000u);
}

// m16n8k16 bf16 MMA, D = A@B + D (fp32 accum)
#define MMA_BF16(d, a, b)                                                     \
    asm volatile("mma.sync.aligned.m16n8k16.row.col.f32.bf16.bf16.f32 "       \
                 "{%0,%1,%2,%3}, {%4,%5,%6,%7}, {%8,%9}, {%0,%1,%2,%3};"      \
                 : "+f"((d)[0]), "+f"((d)[1]), "+f"((d)[2]), "+f"((d)[3])     \
                 : "r"((a)[0]), "r"((a)[1]), "r"((a)[2]), "r"((a)[3]),        \
                   "r"((b)[0]), "r"((b)[1]))

// ---------------------------------------------------------------------------
// Kernel 1: build M = G_comb @ matrix; emit packed-bf16 hi/lo B FRAGMENTS.
// G_comb = I @ G_0 @ ... @ G_31 ; right-multiplying by G_q updates COLUMNS:
//   col_i' = col_i*c + col_j*s ;  col_j' = -col_i*s + col_j*c
// Degenerate i==j (JAX .at sequence leaves G[i,i] = sin): col_i' = col_i*s
// ---------------------------------------------------------------------------
__global__ void build_M_kernel(const float* __restrict__ matrix,
                               const float* __restrict__ thetas,
                               const float* __restrict__ tscale,
                               const int*   __restrict__ pairs) {
    __shared__ float Gs[64][65];
    __shared__ float Mat[64][64];
    __shared__ float Msh[64][64];
    __shared__ float ssin[ROTN], scos[ROTN];
    __shared__ int   sij[ROTN][2];
    const int tid = threadIdx.x;   // 256 threads

    for (int i = tid; i < 64 * 64; i += 256)
        Mat[i >> 6][i & 63] = matrix[i];

    if (tid < ROTN) {                      // sincos once, not per-row
        const float th = thetas[tid] * tscale[0];
        float s, c;
        sincosf(th, &s, &c);
        ssin[tid] = s;
        scos[tid] = c;
        sij[tid][0] = pairs[2 * tid];
        sij[tid][1] = pairs[2 * tid + 1];
    }
    if (tid < 64) {
        #pragma unroll
        for (int k = 0; k < 64; k++) Gs[tid][k] = (tid == k) ? 1.0f : 0.0f;
    }
    __syncthreads();

    if (tid < 64) {
        for (int q = 0; q < ROTN; q++) {
            const int   i = sij[q][0];
            const int   j = sij[q][1];
            const float s = ssin[q];
            const float c = scos[q];
            const float ai = Gs[tid][i];
            const float aj = Gs[tid][j];
            if (i != j) {
                Gs[tid][i] = ai * c + aj * s;
                Gs[tid][j] = -ai * s + aj * c;
            } else {
                Gs[tid][i] = ai * s;
            }
        }
    }
    __syncthreads();

    {
        const int r  = tid >> 2;
        const int qq = tid & 3;
        float gr[64];
        #pragma unroll
        for (int k = 0; k < 64; k++) gr[k] = Gs[r][k];
        #pragma unroll
        for (int n0 = 0; n0 < 16; n0++) {
            const int n = qq * 16 + n0;
            float acc = 0.0f;
            #pragma unroll
            for (int k = 0; k < 64; k++) acc = fmaf(gr[k], Mat[k][n], acc);
            Msh[r][n] = acc;
        }
    }
    __syncthreads();

    // emit fragment-ordered B: hi = bf16(M), lo = bf16(M - hi)
    for (int idx = tid; idx < 4 * 8 * 32; idx += 256) {
        const int frag = idx >> 5;           // kt*8 + j
        const int lane = idx & 31;
        const int kt = frag >> 3, j = frag & 7;
        const int g = lane >> 2, tg = lane & 3;
        const int k0 = kt * 16 + 2 * tg;
        const int n  = 8 * j + g;
        uint4 o;
        {
            const float m0 = Msh[k0][n],     m1 = Msh[k0 + 1][n];
            o.x = pack_bf16x2(m0, m1);
            o.z = pack_bf16x2(m0 - bf_lo_f32(o.x), m1 - bf_hi_f32(o.x));
        }
        {
            const float m0 = Msh[k0 + 8][n], m1 = Msh[k0 + 9][n];
            o.y = pack_bf16x2(m0, m1);
            o.w = pack_bf16x2(m0 - bf_lo_f32(o.y), m1 - bf_hi_f32(o.y));
        }
        g_Bfrag[idx] = o;
    }
}

// ---------------------------------------------------------------------------
// Kernel 2: bf16 m16n8k16 mma.sync GEMM (3-term compensated) + RoPE epilogue.
// CTA = 128 threads (4 warps), tile = 128 rows x 64 cols, K = 64 (4 kt).
// Warp w: rows [w*32, w*32+32) = two m16 tiles; 8 n8-tiles cover 64 cols.
// A pre-converted to packed bf16x2 hi/lo AT STAGE TIME, k-pairs permuted
// within each 8-group (order 0,4,1,5,2,6,3,7) so a fragment's (kp, kp+4)
// pair is one LDS.64. Row stride 160 B (== 32 mod 128: g-lanes hit distinct
// banks per 16-lane phase; conflict-free). B fragments pre-built: one
// LDS.128 per (kt,j) carries hi+lo for both k-groups.
// Double-buffered across kt under __launch_bounds__(128, 2).
// Epilogue: RoPE in regs -> conflict-free STS.32 scatter -> LDS.128+STG.128.
// ---------------------------------------------------------------------------
#define A_ROW_U32 40                               // 160 B row stride
#define SM_AH    0                                 // 128*160 = 20480 B
#define SM_AL    20480                             // 20480 B
#define SM_BF    40960                             // 16384 B
#define SM_SC    57344                             // 2048 B
#define SMEM_DYN 59392
#define O_STRIDE 68                                // epilogue scatter stride

__global__ __launch_bounds__(128, 2)
void rotary_mma(const float* __restrict__ x,
                const float* __restrict__ invf,
                float* __restrict__ out) {
    extern __shared__ __align__(16) char dsm[];
    uint32_t* Ah  = (uint32_t*)(dsm + SM_AH);
    uint32_t* Al  = (uint32_t*)(dsm + SM_AL);
    uint4*    Bfs = (uint4*)(dsm + SM_BF);
    float2*   sc  = (float2*)(dsm + SM_SC);

    const int tid  = threadIdx.x;
    const int w    = tid >> 5;
    const int lane = tid & 31;
    const int g    = lane >> 2;     // groupID 0..7
    const int tig  = lane & 3;      // threadID_in_group 0..3

    // ---- stage A: fp32 -> packed bf16x2 hi/lo, k-pair permuted ----
    // chunk idx -> row, kq (4 fp32 = k-pairs 2kq, 2kq+1). Within each kt
    // block of 8 kp's, kp at permuted pos: kpb<4 ? 2*kpb : 2*(kpb-4)+1.
    {
        const float4* xg = (const float4*)(x + (size_t)blockIdx.x * 128 * 64);
        #pragma unroll
        for (int i = 0; i < 16; i++) {
            const int idx = i * 128 + tid;        // 16B chunk id, 2048 total
            const int row = idx >> 4;
            const int kq  = idx & 15;
            const float4 v = xg[idx];
            const int kp0 = 2 * kq;               // even kpb in {0,2,4,6}
            const int kt  = kp0 >> 3;
            const int kpb0 = kp0 & 7, kpb1 = kpb0 + 1;
            const int pos0 = (kpb0 < 4) ? 2 * kpb0 : 2 * (kpb0 - 4) + 1;
            const int pos1 = (kpb1 < 4) ? 2 * kpb1 : 2 * (kpb1 - 4) + 1;
            const int base = row * A_ROW_U32 + kt * 8;
            const uint32_t h0 = pack_bf16x2(v.x, v.y);
            const uint32_t h1 = pack_bf16x2(v.z, v.w);
            Ah[base + pos0] = h0;
            Ah[base + pos1] = h1;
            Al[base + pos0] = pack_bf16x2(v.x - bf_lo_f32(h0), v.y - bf_hi_f32(h0));
            Al[base + pos1] = pack_bf16x2(v.z - bf_lo_f32(h1), v.w - bf_hi_f32(h1));
        }
    }

    // ---- stage B fragments: 1024 uint4, 8 per thread ----
    {
        #pragma unroll
        for (int i = 0; i < 8; i++) {
            const int idx = tid + 128 * i;
            Bfs[idx] = g_Bfrag[idx];
        }
    }

    // ---- sincos table: 8 tokens x 32 freqs ----
    {
        #pragma unroll
        for (int e = 0; e < 2; e++) {
            const int idx = tid * 2 + e;          // 256 entries
            const int t = idx >> 5, m = idx & 31;
            const int pos = (blockIdx.x * 8 + t) & (SEQ - 1);
            float sn, cs;
            sincosf((float)pos * invf[m], &sn, &cs);
            sc[idx] = make_float2(sn, cs);
        }
    }
    __syncthreads();

    // ---- mainloop: 4 kt steps, double-buffered A frags + B frags ----
    float acc[2][8][4];
    #pragma unroll
    for (int mt = 0; mt < 2; mt++)
        #pragma unroll
        for (int j = 0; j < 8; j++)
            #pragma unroll
            for (int q = 0; q < 4; q++) acc[mt][j][q] = 0.0f;

    // A fragment base (u32 index): row (w*32 + mt*16 + g [+8]), offset 2*tig
    const int arow = (w * 32 + g) * A_ROW_U32 + 2 * tig;
    const uint4* Bbase = Bfs + lane;

    // frag regs: [buf][mt][4] = {a0,a1,a2,a3}; a0,a2 from row g; a1,a3 row g+8
    uint32_t fh[2][2][4], fl[2][2][4];
    uint4 pb[2][8];

    // prefetch kt = 0
    #pragma unroll
    for (int mt = 0; mt < 2; mt++) {
        const int ro = arow + mt * 16 * A_ROW_U32;
        uint2 t0 = *(const uint2*)(Ah + ro);
        uint2 t1 = *(const uint2*)(Ah + ro + 8 * A_ROW_U32);
        fh[0][mt][0] = t0.x; fh[0][mt][2] = t0.y;
        fh[0][mt][1] = t1.x; fh[0][mt][3] = t1.y;
        t0 = *(const uint2*)(Al + ro);
        t1 = *(const uint2*)(Al + ro + 8 * A_ROW_U32);
        fl[0][mt][0] = t0.x; fl[0][mt][2] = t0.y;
        fl[0][mt][1] = t1.x; fl[0][mt][3] = t1.y;
    }
    #pragma unroll
    for (int j = 0; j < 8; j++) pb[0][j] = Bbase[j * 32];

    #pragma unroll
    for (int kt = 0; kt < 4; kt++) {
        const int cur = kt & 1, nxt = cur ^ 1;
        if (kt < 3) {
            #pragma unroll
            for (int mt = 0; mt < 2; mt++) {
                const int ro = arow + mt * 16 * A_ROW_U32 + (kt + 1) * 8;
                uint2 t0 = *(const uint2*)(Ah + ro);
                uint2 t1 = *(const uint2*)(Ah + ro + 8 * A_ROW_U32);
                fh[nxt][mt][0] = t0.x; fh[nxt][mt][2] = t0.y;
                fh[nxt][mt][1] = t1.x; fh[nxt][mt][3] = t1.y;
                t0 = *(const uint2*)(Al + ro);
                t1 = *(const uint2*)(Al + ro + 8 * A_ROW_U32);
                fl[nxt][mt][0] = t0.x; fl[nxt][mt][2] = t0.y;
                fl[nxt][mt][1] = t1.x; fl[nxt][mt][3] = t1.y;
            }
            #pragma unroll
            for (int j = 0; j < 8; j++)
                pb[nxt][j] = Bbase[((kt + 1) * 8 + j) * 32];
        }

        #pragma unroll
        for (int j = 0; j < 8; j++) {
            const uint4 bf = pb[cur][j];
            uint32_t bh[2] = {bf.x, bf.y};
            uint32_t bl[2] = {bf.z, bf.w};
            #pragma unroll
            for (int mt = 0; mt < 2; mt++) {
                MMA_BF16(acc[mt][j], fh[cur][mt], bh);   // xh @ Mh
                MMA_BF16(acc[mt][j], fl[cur][mt], bh);   // xl @ Mh
                MMA_BF16(acc[mt][j], fh[cur][mt], bl);   // xh @ Ml
            }
        }
    }

    // ---- epilogue: RoPE + *32 in regs, STS.32 scatter (conflict-free),
    //      then coalesced LDS.128 -> STG.128 ----
    __syncthreads();                                     // A/B reads done
    float* Osm = (float*)dsm;                            // reuse as scratch
    #pragma unroll
    for (int mt = 0; mt < 2; mt++) {
        const int tok = 2 * w + mt;
        const int r0 = w * 32 + mt * 16 + g;
        #pragma unroll
        for (int j = 0; j < 8; j++) {
            const int m = 4 * j + tig;
            const float2 scm = sc[tok * 32 + m];         // (sin, cos)
            const float* a = acc[mt][j];
            Osm[r0 * O_STRIDE + m]            = (a[0] * scm.y - a[1] * scm.x) * 32.0f;
            Osm[r0 * O_STRIDE + m + 32]       = (a[0] * scm.x + a[1] * scm.y) * 32.0f;
            Osm[(r0 + 8) * O_STRIDE + m]      = (a[2] * scm.y - a[3] * scm.x) * 32.0f;
            Osm[(r0 + 8) * O_STRIDE + m + 32] = (a[2] * scm.x + a[3] * scm.y) * 32.0f;
        }
    }
    __syncthreads();

    {
        float4* og = (float4*)(out + (size_t)blockIdx.x * 128 * 64);
        #pragma unroll
        for (int i = 0; i < 16; i++) {
            const int idx = i * 128 + tid;        // 16B chunk id, 2048 total
            const int row = idx >> 4;
            const int kq  = idx & 15;
            og[idx] = *(const float4*)(Osm + row * O_STRIDE + kq * 4);
        }
    }
}

// ---------------------------------------------------------------------------
extern "C" void kernel_launch(void* const* d_in, const int* in_sizes, int n_in,
                              void* d_out, int out_size) {
    const float* x      = (const float*)d_in[0];
    const float* matrix = (const float*)d_in[1];
    const float* thetas = (const float*)d_in[2];
    const float* tscale = (const float*)d_in[3];
    const float* invf   = (const float*)d_in[4];
    const int*   pairs  = (const int*)d_in[5];
    float* out = (float*)d_out;

    static bool attr_set = false;
    if (!attr_set) {
        cudaFuncSetAttribute(rotary_mma,
                             cudaFuncAttributeMaxDynamicSharedMemorySize,
                             SMEM_DYN);
        attr_set = true;
    }

    const int nrows  = in_sizes[0] / D;      // 524288
    const int blocks = nrows / 128;          // 4096

    build_M_kernel<<<1, 256>>>(matrix, thetas, tscale, pairs);
    rotary_mma<<<blocks, 128, SMEM_DYN>>>(x, invf, out);
}